// round 4
// baseline (speedup 1.0000x reference)
#include <cuda_runtime.h>
#include <math.h>

#define K_TOP    6000
#define CAND_CAP 16384
#define NMS_CAP  1024
#define HBINS    4096      // top 12 bits of transformed score
#define RC       8

// ---------------- scratch (device globals; no allocations) ----------------
__device__ unsigned int       g_hist[HBINS];
__device__ unsigned int       g_meta[8];     // [3] = candidate counter
__device__ unsigned long long g_cand[CAND_CAP];

// order-preserving float<->uint transform
__device__ __forceinline__ unsigned int f2u(float f) {
    unsigned int b = __float_as_uint(f);
    return b ^ ((b & 0x80000000u) ? 0xFFFFFFFFu : 0x80000000u);
}
__device__ __forceinline__ float u2f(unsigned int u) {
    unsigned int b = (u & 0x80000000u) ? (u ^ 0x80000000u) : ~u;
    return __uint_as_float(b);
}

// ---------------- kernel 1: 12-bit histogram of fg scores ----------------
__global__ void k_hist(const float* __restrict__ probs, int n_groups) {
    __shared__ unsigned int sh[HBINS];
    for (int k = threadIdx.x; k < HBINS; k += blockDim.x) sh[k] = 0u;
    __syncthreads();

    const float4* __restrict__ p4 = (const float4*)probs;
    int stride = gridDim.x * blockDim.x;
    for (int g = blockIdx.x * blockDim.x + threadIdx.x; g < n_groups; g += stride) {
        float4 A = p4[g * 3 + 0], B = p4[g * 3 + 1], C = p4[g * 3 + 2];
        float s[8] = {A.y, A.z, B.x, B.y, B.w, C.x, C.z, C.w};
#pragma unroll
        for (int k = 0; k < 8; k++) {
            unsigned int bin = f2u(s[k]) >> 20;
            unsigned int act = __activemask();
            unsigned int peers = __match_any_sync(act, bin);
            int leader = __ffs(peers) - 1;
            if ((threadIdx.x & 31) == leader)
                atomicAdd(&sh[bin], (unsigned int)__popc(peers));
        }
    }
    __syncthreads();
    for (int k = threadIdx.x; k < HBINS; k += blockDim.x) {
        unsigned int v = sh[k];
        if (v) atomicAdd(&g_hist[k], v);
    }
}

// ------- kernel 2: per-block threshold prologue + candidate collection -------
__global__ void k_collect(const float* __restrict__ probs, int n_groups) {
    __shared__ unsigned int ssum[256];
    __shared__ unsigned int s_t;
    int tid = threadIdx.x;
    int lane = tid & 31;

    // threshold bin from g_hist (each block computes it independently; L2-hot)
    unsigned int cs = 0;
    int base = tid * (HBINS / 256);
#pragma unroll
    for (int k = 0; k < HBINS / 256; k++) cs += g_hist[base + k];
    ssum[tid] = cs; __syncthreads();
    for (int off = 1; off < 256; off <<= 1) {      // inclusive suffix sum
        unsigned int v = (tid + off < 256) ? ssum[tid + off] : 0u;
        __syncthreads();
        ssum[tid] += v;
        __syncthreads();
    }
    unsigned int excl = (tid < 255) ? ssum[tid + 1] : 0u;
    if (ssum[tid] >= (unsigned)K_TOP && excl < (unsigned)K_TOP) {   // unique crossing
        unsigned int run = excl;
        for (int k = HBINS / 256 - 1; k >= 0; k--) {
            run += g_hist[base + k];
            if (run >= (unsigned)K_TOP) { s_t = (unsigned int)(base + k); break; }
        }
    }
    __syncthreads();
    unsigned int t = s_t;

    const float4* __restrict__ p4 = (const float4*)probs;
    int stride = gridDim.x * blockDim.x;
    for (int g = blockIdx.x * blockDim.x + tid; g < n_groups; g += stride) {
        float4 A = p4[g * 3 + 0], B = p4[g * 3 + 1], C = p4[g * 3 + 2];
        float s[8] = {A.y, A.z, B.x, B.y, B.w, C.x, C.z, C.w};
#pragma unroll
        for (int k = 0; k < 8; k++) {
            unsigned int u = f2u(s[k]);
            bool e = (u >> 20) >= t;
            unsigned int act = __activemask();
            unsigned int ball = __ballot_sync(act, e);
            if (ball) {
                int leader = __ffs(ball) - 1;
                unsigned int posb = 0;
                if (lane == leader)
                    posb = atomicAdd(&g_meta[3], (unsigned int)__popc(ball));
                posb = __shfl_sync(act, posb, leader);
                if (e) {
                    unsigned int my = posb + __popc(ball & ((1u << lane) - 1u));
                    if (my < CAND_CAP) {
                        unsigned int flat = (unsigned int)((g * 4 + (k >> 1)) * 2 + (k & 1));
                        g_cand[my] = ((unsigned long long)u << 32) |
                                     (unsigned long long)(0xFFFFFFFFu - flat);
                    }
                }
            }
        }
    }
}

// ------- kernel 3: exact rank by counting + fused decode/write -------
__global__ void k_rankdec(const float* __restrict__ deltas,
                          const float* __restrict__ anchors,
                          float* __restrict__ out, int n_anchors) {
    __shared__ unsigned int partial[RC][8];
    int m = (int)min(g_meta[3], (unsigned int)CAND_CAP);
    int bc = blockIdx.x * RC;
    if (bc >= m) return;

    unsigned long long cand[RC];
#pragma unroll
    for (int c = 0; c < RC; c++)
        cand[c] = (bc + c < m) ? g_cand[bc + c] : 0xFFFFFFFFFFFFFFFFULL;
    unsigned int cnt[RC];
#pragma unroll
    for (int c = 0; c < RC; c++) cnt[c] = 0u;

    for (int j = threadIdx.x; j < m; j += 256) {
        unsigned long long k = g_cand[j];
#pragma unroll
        for (int c = 0; c < RC; c++) cnt[c] += (k > cand[c]) ? 1u : 0u;
    }
    int lane = threadIdx.x & 31, w = threadIdx.x >> 5;
#pragma unroll
    for (int c = 0; c < RC; c++) {
#pragma unroll
        for (int off = 16; off > 0; off >>= 1)
            cnt[c] += __shfl_down_sync(0xFFFFFFFFu, cnt[c], off);
        if (lane == 0) partial[c][w] = cnt[c];
    }
    __syncthreads();

    if (threadIdx.x < RC) {
        int c = threadIdx.x;
        if (bc + c < m) {
            unsigned int rank = 0;
#pragma unroll
            for (int k = 0; k < 8; k++) rank += partial[c][k];
            if (rank < K_TOP) {
                int r = (int)rank;
                unsigned long long key = cand[c];
                unsigned int u = (unsigned int)(key >> 32);
                unsigned int flat = 0xFFFFFFFFu - (unsigned int)(key & 0xFFFFFFFFu);
                int prop = (int)(flat >> 1);
                int cls = (int)(flat & 1u) + 1;
                float score = u2f(u);
                int b = prop / n_anchors;
                int ai = prop - b * n_anchors;

                const float* a  = anchors + (size_t)ai * 4;
                const float* dl = deltas + (size_t)prop * 4;
                float d0 = dl[0] * 0.1f, d1 = dl[1] * 0.1f;
                float d2 = dl[2] * 0.2f, d3 = dl[3] * 0.2f;

                const float inv = 1.0f / 512.0f;
                float ay1 = a[0] * inv, ax1 = a[1] * inv;
                float ay2 = a[2] * inv, ax2 = a[3] * inv;
                float h = ay2 - ay1;
                float w2 = ax2 - ax1;
                float cy = ay1 + 0.5f * h + d0 * h;
                float cx = ax1 + 0.5f * w2 + d1 * w2;
                h = h * expf(d2);
                w2 = w2 * expf(d3);
                float y1 = cy - 0.5f * h;
                float x1 = cx - 0.5f * w2;
                float y2 = y1 + h;
                float x2 = x1 + w2;
                y1 = fminf(fmaxf(y1 * 512.0f, 0.0f), 512.0f);
                x1 = fminf(fmaxf(x1 * 512.0f, 0.0f), 512.0f);
                y2 = fminf(fmaxf(y2 * 512.0f, 0.0f), 512.0f);
                x2 = fminf(fmaxf(x2 * 512.0f, 0.0f), 512.0f);

                out[r * 6 + 0] = y1;
                out[r * 6 + 1] = x1;
                out[r * 6 + 2] = y2;
                out[r * 6 + 3] = x2;
                out[r * 6 + 4] = score;
                out[r * 6 + 5] = 1.0f;                 // keep (finalized by NMS)
                out[K_TOP * 6 + r] = (float)cls;       // class_ids
                out[K_TOP * 7 + r] = (float)b;         // batch ids
            }
        }
    }
}

// ------- kernel 4: per-(batch,class) NMS via transposed masks + Jacobi fixpoint -------
// dynamic smem: by1|bx1|by2|bx2 (f32 x NMS_CAP), spos (i32 x NMS_CAP),
//               suppT (u32 x NMS_CAP x 32)  -- suppT[i] bit j: j<i and iou(i,j)>=0.5
__global__ void k_nms(float* __restrict__ out) {
    extern __shared__ unsigned char dyn[];
    float* sy1 = (float*)dyn;
    float* sx1 = sy1 + NMS_CAP;
    float* sy2 = sx1 + NMS_CAP;
    float* sx2 = sy2 + NMS_CAP;
    int* spos  = (int*)(sx2 + NMS_CAP);
    unsigned int* suppT = (unsigned int*)(spos + NMS_CAP);   // [NMS_CAP][32]

    __shared__ int s_wcnt[8], s_woff[8], s_n, s_changed;
    __shared__ unsigned int kold[32], knew[32];

    int tid = threadIdx.x;

    // cleanup scratch for next graph replay (16 blocks x 256 threads = 4096 bins)
    g_hist[blockIdx.x * (HBINS / 16) + tid] = 0u;
    if (blockIdx.x == 0 && tid == 0) g_meta[3] = 0u;

    int bb = blockIdx.x >> 1;
    int cls = (int)(blockIdx.x & 1) + 1;
    float bbf = (float)bb, clsf = (float)cls;

    if (tid == 0) s_n = 0;
    __syncthreads();

    // stable compaction of this group's entries, in global score order
    for (int base = 0; base < K_TOP; base += 256) {
        int r = base + tid;
        bool m = false;
        float y1 = 0.f, x1 = 0.f, y2 = 0.f, x2 = 0.f;
        if (r < K_TOP) {
            float cf = out[K_TOP * 6 + r];
            float bf = out[K_TOP * 7 + r];
            m = (bf == bbf) && (cf == clsf);
            if (m) {
                y1 = out[r * 6 + 0]; x1 = out[r * 6 + 1];
                y2 = out[r * 6 + 2]; x2 = out[r * 6 + 3];
            }
        }
        unsigned int ball = __ballot_sync(0xFFFFFFFFu, m);
        int lane = tid & 31, w = tid >> 5;
        if (lane == 0) s_wcnt[w] = __popc(ball);
        __syncthreads();
        if (tid == 0) {
            int acc = s_n;
            for (int k = 0; k < 8; k++) { s_woff[k] = acc; acc += s_wcnt[k]; }
            s_n = acc;
        }
        __syncthreads();
        if (m) {
            int p = s_woff[w] + __popc(ball & ((1u << lane) - 1u));
            if (p < NMS_CAP) {
                sy1[p] = y1; sx1[p] = x1; sy2[p] = y2; sx2[p] = x2;
                spos[p] = r;
            }
        }
        __syncthreads();
    }

    int n = min(s_n, NMS_CAP);
    int nw = (n + 31) >> 5;

    // transposed suppression mask, evenly distributed (i, word) tasks.
    // suppT[i][w] bit b set iff j = 32w+b < i and iou(i,j) >= 0.5
    for (int t = tid; t < n * nw; t += 256) {
        int i = t / nw;
        int w = t - i * nw;
        int iw_hi = i >> 5;
        if (w > iw_hi) { suppT[i * 32 + w] = 0u; continue; }
        float iy1 = sy1[i], ix1 = sx1[i], iy2 = sy2[i], ix2 = sx2[i];
        float ia = (iy2 - iy1 + 1.0f) * (ix2 - ix1 + 1.0f);
        int jmax = i - (w << 5);              // bits with j < i (>=32 means all)
        unsigned int mw = 0u;
#pragma unroll 8
        for (int b = 0; b < 32; b++) {
            if (b < jmax) {
                int j = (w << 5) + b;
                float ih = fminf(iy2, sy2[j]) - fmaxf(iy1, sy1[j]) + 1.0f;
                float iww = fminf(ix2, sx2[j]) - fmaxf(ix1, sx1[j]) + 1.0f;
                ih = fmaxf(ih, 0.0f); iww = fmaxf(iww, 0.0f);
                float inter = ih * iww;
                float ja = (sy2[j] - sy1[j] + 1.0f) * (sx2[j] - sx1[j] + 1.0f);
                if (inter >= 0.5f * (ia + ja - inter)) mw |= (1u << b);
            }
        }
        suppT[i * 32 + w] = mw;
    }

    // init keep = all alive for i < n
    if (tid < 32) {
        unsigned int v;
        if (tid < (n >> 5)) v = 0xFFFFFFFFu;
        else if (tid == (n >> 5)) v = (n & 31) ? ((1u << (n & 31)) - 1u) : 0u;
        else v = 0u;
        kold[tid] = v;
    }
    __syncthreads();

    // Jacobi fixpoint: keep[i] = ((suppT[i] & keep) == 0). Unique fixpoint = greedy NMS.
    for (int iter = 0; iter < NMS_CAP + 2; iter++) {
        if (tid == 0) s_changed = 0;
        __syncthreads();
        for (int base = 0; base < n; base += 256) {
            int i = base + tid;
            bool alive = false;
            if (i < n) {
                unsigned int sup = 0u;
                int hi = i >> 5;
                for (int w = 0; w <= hi; w++)
                    sup |= (suppT[i * 32 + w] & kold[w]);
                alive = (sup == 0u);
            }
            unsigned int ball = __ballot_sync(0xFFFFFFFFu, alive);
            if ((tid & 31) == 0 && i < n) knew[i >> 5] = ball;
        }
        __syncthreads();
        if (tid < 32 && tid < nw) {
            if (knew[tid] != kold[tid]) { s_changed = 1; }
            kold[tid] = knew[tid];
        }
        __syncthreads();
        if (!s_changed) break;
    }

    for (int j = tid; j < n; j += 256)
        out[spos[j] * 6 + 5] = ((kold[j >> 5] >> (j & 31)) & 1u) ? 1.0f : 0.0f;
}

// ---------------- launch ----------------
extern "C" void kernel_launch(void* const* d_in, const int* in_sizes, int n_in,
                              void* d_out, int out_size) {
    const float* probs   = (const float*)d_in[0];
    const float* deltas  = (const float*)d_in[1];
    const float* anchors = (const float*)d_in[2];
    float* out = (float*)d_out;

    int n_prop    = in_sizes[0] / 3;
    int n_anchors = in_sizes[2] / 4;
    int n_groups  = n_prop / 4;          // 4 props (12 floats = 3 float4) per thread-step

    const int nms_smem = NMS_CAP * (4 * 4 + 4 + 32 * 4);   // 151552 bytes
    cudaFuncSetAttribute(k_nms, cudaFuncAttributeMaxDynamicSharedMemorySize, nms_smem);

    k_hist<<<148, 512>>>(probs, n_groups);
    k_collect<<<296, 256>>>(probs, n_groups);
    k_rankdec<<<CAND_CAP / RC, 256>>>(deltas, anchors, out, n_anchors);
    k_nms<<<16, 256, nms_smem>>>(out);
}

// round 5
// speedup vs baseline: 1.3894x; 1.3894x over previous
#include <cuda_runtime.h>
#include <math.h>

#define K_TOP    6000
#define CAND_CAP 16384
#define NMS_CAP  1024
#define HBINS    4096      // top 12 bits of transformed score
#define RC       8
#define MSTRIDE  33        // padded mask row stride (kills 32-way bank conflicts)
#define NGROUPS  16

// ---------------- scratch (device globals; no allocations) ----------------
__device__ unsigned int       g_hist[HBINS];
__device__ unsigned int       g_meta[8];     // [3] = candidate counter
__device__ unsigned long long g_cand[CAND_CAP];
__device__ float4             g_gbox[NGROUPS * NMS_CAP];
__device__ int                g_gpos[NGROUPS * NMS_CAP];
__device__ unsigned int       g_gcnt[NGROUPS];

// order-preserving float<->uint transform
__device__ __forceinline__ unsigned int f2u(float f) {
    unsigned int b = __float_as_uint(f);
    return b ^ ((b & 0x80000000u) ? 0xFFFFFFFFu : 0x80000000u);
}
__device__ __forceinline__ float u2f(unsigned int u) {
    unsigned int b = (u & 0x80000000u) ? (u ^ 0x80000000u) : ~u;
    return __uint_as_float(b);
}
__device__ __forceinline__ unsigned int group_of(unsigned long long key,
                                                 unsigned int n_anch) {
    unsigned int flat = 0xFFFFFFFFu - (unsigned int)(key & 0xFFFFFFFFu);
    unsigned int prop = flat >> 1;
    return (prop / n_anch) * 2u + (flat & 1u);
}

// ---------------- kernel 1: 12-bit histogram of fg scores ----------------
__global__ void k_hist(const float* __restrict__ probs, int n_groups) {
    __shared__ unsigned int sh[HBINS];
    for (int k = threadIdx.x; k < HBINS; k += blockDim.x) sh[k] = 0u;
    __syncthreads();

    const float4* __restrict__ p4 = (const float4*)probs;
    int stride = gridDim.x * blockDim.x;
    for (int g = blockIdx.x * blockDim.x + threadIdx.x; g < n_groups; g += stride) {
        float4 A = p4[g * 3 + 0], B = p4[g * 3 + 1], C = p4[g * 3 + 2];
        float s[8] = {A.y, A.z, B.x, B.y, B.w, C.x, C.z, C.w};
#pragma unroll
        for (int k = 0; k < 8; k++) {
            unsigned int bin = f2u(s[k]) >> 20;
            unsigned int act = __activemask();
            unsigned int peers = __match_any_sync(act, bin);
            int leader = __ffs(peers) - 1;
            if ((threadIdx.x & 31) == leader)
                atomicAdd(&sh[bin], (unsigned int)__popc(peers));
        }
    }
    __syncthreads();
    for (int k = threadIdx.x; k < HBINS; k += blockDim.x) {
        unsigned int v = sh[k];
        if (v) atomicAdd(&g_hist[k], v);
    }
}

// ------- kernel 2: per-block threshold prologue + candidate collection -------
__global__ void k_collect(const float* __restrict__ probs, int n_groups) {
    __shared__ unsigned int ssum[256];
    __shared__ unsigned int s_t;
    int tid = threadIdx.x;
    int lane = tid & 31;

    unsigned int cs = 0;
    int base = tid * (HBINS / 256);
#pragma unroll
    for (int k = 0; k < HBINS / 256; k++) cs += g_hist[base + k];
    ssum[tid] = cs; __syncthreads();
    for (int off = 1; off < 256; off <<= 1) {      // inclusive suffix sum
        unsigned int v = (tid + off < 256) ? ssum[tid + off] : 0u;
        __syncthreads();
        ssum[tid] += v;
        __syncthreads();
    }
    unsigned int excl = (tid < 255) ? ssum[tid + 1] : 0u;
    if (ssum[tid] >= (unsigned)K_TOP && excl < (unsigned)K_TOP) {   // unique crossing
        unsigned int run = excl;
        for (int k = HBINS / 256 - 1; k >= 0; k--) {
            run += g_hist[base + k];
            if (run >= (unsigned)K_TOP) { s_t = (unsigned int)(base + k); break; }
        }
    }
    __syncthreads();
    unsigned int t = s_t;

    const float4* __restrict__ p4 = (const float4*)probs;
    int stride = gridDim.x * blockDim.x;
    for (int g = blockIdx.x * blockDim.x + tid; g < n_groups; g += stride) {
        float4 A = p4[g * 3 + 0], B = p4[g * 3 + 1], C = p4[g * 3 + 2];
        float s[8] = {A.y, A.z, B.x, B.y, B.w, C.x, C.z, C.w};
#pragma unroll
        for (int k = 0; k < 8; k++) {
            unsigned int u = f2u(s[k]);
            bool e = (u >> 20) >= t;
            unsigned int act = __activemask();
            unsigned int ball = __ballot_sync(act, e);
            if (ball) {
                int leader = __ffs(ball) - 1;
                unsigned int posb = 0;
                if (lane == leader)
                    posb = atomicAdd(&g_meta[3], (unsigned int)__popc(ball));
                posb = __shfl_sync(act, posb, leader);
                if (e) {
                    unsigned int my = posb + __popc(ball & ((1u << lane) - 1u));
                    if (my < CAND_CAP) {
                        unsigned int flat = (unsigned int)((g * 4 + (k >> 1)) * 2 + (k & 1));
                        g_cand[my] = ((unsigned long long)u << 32) |
                                     (unsigned long long)(0xFFFFFFFFu - flat);
                    }
                }
            }
        }
    }
}

// --- kernel 3: exact global + within-group rank, fused decode + group scatter ---
__global__ void k_rankdec(const float* __restrict__ deltas,
                          const float* __restrict__ anchors,
                          float* __restrict__ out, int n_anchors) {
    __shared__ unsigned int partial[RC][8], partg[RC][8];
    int m = (int)min(g_meta[3], (unsigned int)CAND_CAP);
    int bc = blockIdx.x * RC;
    if (bc >= m) return;

    unsigned int n_anch = (unsigned int)n_anchors;
    unsigned long long cand[RC];
    unsigned int cgrp[RC];
#pragma unroll
    for (int c = 0; c < RC; c++) {
        cand[c] = (bc + c < m) ? g_cand[bc + c] : 0xFFFFFFFFFFFFFFFFULL;
        cgrp[c] = group_of(cand[c], n_anch);
    }
    unsigned int cnt[RC], cntg[RC];
#pragma unroll
    for (int c = 0; c < RC; c++) { cnt[c] = 0u; cntg[c] = 0u; }

    for (int j = threadIdx.x; j < m; j += 256) {
        unsigned long long k = g_cand[j];
        unsigned int gj = group_of(k, n_anch);
#pragma unroll
        for (int c = 0; c < RC; c++) {
            bool gt = (k > cand[c]);
            cnt[c] += gt ? 1u : 0u;
            cntg[c] += (gt && gj == cgrp[c]) ? 1u : 0u;
        }
    }
    int lane = threadIdx.x & 31, w = threadIdx.x >> 5;
#pragma unroll
    for (int c = 0; c < RC; c++) {
#pragma unroll
        for (int off = 16; off > 0; off >>= 1) {
            cnt[c]  += __shfl_down_sync(0xFFFFFFFFu, cnt[c], off);
            cntg[c] += __shfl_down_sync(0xFFFFFFFFu, cntg[c], off);
        }
        if (lane == 0) { partial[c][w] = cnt[c]; partg[c][w] = cntg[c]; }
    }
    __syncthreads();

    if (threadIdx.x < RC) {
        int c = threadIdx.x;
        if (bc + c < m) {
            unsigned int rank = 0, grank = 0;
#pragma unroll
            for (int k = 0; k < 8; k++) { rank += partial[c][k]; grank += partg[c][k]; }
            if (rank < K_TOP) {
                int r = (int)rank;
                unsigned long long key = cand[c];
                unsigned int u = (unsigned int)(key >> 32);
                unsigned int flat = 0xFFFFFFFFu - (unsigned int)(key & 0xFFFFFFFFu);
                int prop = (int)(flat >> 1);
                int cls = (int)(flat & 1u) + 1;
                float score = u2f(u);
                int b = prop / n_anchors;
                int ai = prop - b * n_anchors;

                const float* a  = anchors + (size_t)ai * 4;
                const float* dl = deltas + (size_t)prop * 4;
                float d0 = dl[0] * 0.1f, d1 = dl[1] * 0.1f;
                float d2 = dl[2] * 0.2f, d3 = dl[3] * 0.2f;

                const float inv = 1.0f / 512.0f;
                float ay1 = a[0] * inv, ax1 = a[1] * inv;
                float ay2 = a[2] * inv, ax2 = a[3] * inv;
                float h = ay2 - ay1;
                float w2 = ax2 - ax1;
                float cy = ay1 + 0.5f * h + d0 * h;
                float cx = ax1 + 0.5f * w2 + d1 * w2;
                h = h * expf(d2);
                w2 = w2 * expf(d3);
                float y1 = cy - 0.5f * h;
                float x1 = cx - 0.5f * w2;
                float y2 = y1 + h;
                float x2 = x1 + w2;
                y1 = fminf(fmaxf(y1 * 512.0f, 0.0f), 512.0f);
                x1 = fminf(fmaxf(x1 * 512.0f, 0.0f), 512.0f);
                y2 = fminf(fmaxf(y2 * 512.0f, 0.0f), 512.0f);
                x2 = fminf(fmaxf(x2 * 512.0f, 0.0f), 512.0f);

                out[r * 6 + 0] = y1;
                out[r * 6 + 1] = x1;
                out[r * 6 + 2] = y2;
                out[r * 6 + 3] = x2;
                out[r * 6 + 4] = score;
                out[r * 6 + 5] = 1.0f;                 // keep (finalized by NMS)
                out[K_TOP * 6 + r] = (float)cls;       // class_ids
                out[K_TOP * 7 + r] = (float)b;         // batch ids

                int grp = b * 2 + (int)(flat & 1u);
                atomicAdd(&g_gcnt[grp], 1u);
                if (grank < NMS_CAP) {
                    g_gbox[grp * NMS_CAP + grank] = make_float4(y1, x1, y2, x2);
                    g_gpos[grp * NMS_CAP + grank] = r;
                }
            }
        }
    }
}

// ------- kernel 4: per-group NMS on pre-sorted boxes + scratch cleanup -------
// dynamic smem: sy1|sx1|sy2|sx2|sarea (f32 x NMS_CAP), spos (i32 x NMS_CAP),
//               mask (u32 x NMS_CAP x MSTRIDE)
__global__ void k_nms(float* __restrict__ out) {
    extern __shared__ unsigned char dyn[];
    float* sy1   = (float*)dyn;
    float* sx1   = sy1 + NMS_CAP;
    float* sy2   = sx1 + NMS_CAP;
    float* sx2   = sy2 + NMS_CAP;
    float* sarea = sx2 + NMS_CAP;
    int* spos    = (int*)(sarea + NMS_CAP);
    unsigned int* mask = (unsigned int*)(spos + NMS_CAP);   // [NMS_CAP][MSTRIDE]

    __shared__ unsigned int s_remv[32];

    int tid = threadIdx.x;
    int grp = blockIdx.x;

    // cleanup scratch for next graph replay
    if (tid < HBINS / NGROUPS) g_hist[grp * (HBINS / NGROUPS) + tid] = 0u;
    if (grp == 0 && tid == 256) g_meta[3] = 0u;

    int n = min((int)g_gcnt[grp], NMS_CAP);

    // load this group's pre-sorted boxes (coalesced float4)
    for (int i = tid; i < n; i += blockDim.x) {
        float4 bx = g_gbox[grp * NMS_CAP + i];
        sy1[i] = bx.x; sx1[i] = bx.y; sy2[i] = bx.z; sx2[i] = bx.w;
        sarea[i] = (bx.z - bx.x + 1.0f) * (bx.w - bx.y + 1.0f);
        spos[i] = g_gpos[grp * NMS_CAP + i];
    }
    __syncthreads();
    if (tid == 0) g_gcnt[grp] = 0u;     // clear after everyone has read n

    int nw = (n + 31) >> 5;

    // build forward suppression masks: mask[i][w] bit b set iff j=32w+b, j>i,
    // iou(i,j)>=0.5.  Flatten t = w*n + i (i fastest): lanes share w & j
    // (broadcast), take consecutive i (conflict-free with MSTRIDE=33).
    int total = nw * n;
    for (int t = tid; t < total; t += blockDim.x) {
        int w = t / n;
        int i = t - w * n;
        if (w < (i >> 5)) { mask[i * MSTRIDE + w] = 0u; continue; }
        float iy1 = sy1[i], ix1 = sx1[i], iy2 = sy2[i], ix2 = sx2[i];
        float ia = sarea[i];
        unsigned int mw = 0u;
        int jb = w << 5;
#pragma unroll 8
        for (int b = 0; b < 32; b++) {
            int j = jb + b;
            if (j > i && j < n) {
                float ih  = fminf(iy2, sy2[j]) - fmaxf(iy1, sy1[j]) + 1.0f;
                float iw2 = fminf(ix2, sx2[j]) - fmaxf(ix1, sx1[j]) + 1.0f;
                ih = fmaxf(ih, 0.0f); iw2 = fmaxf(iw2, 0.0f);
                float inter = ih * iw2;
                if (inter >= 0.5f * (ia + sarea[j] - inter)) mw |= (1u << b);
            }
        }
        mask[i * MSTRIDE + w] = mw;
    }
    __syncthreads();

    // sequential greedy bit-reduce by warp 0; lane l owns removal word l
    if (tid < 32) {
        unsigned int remv = 0u;
        for (int i = 0; i < n; i++) {
            unsigned int wv = __shfl_sync(0xFFFFFFFFu, remv, i >> 5);
            if (!((wv >> (i & 31)) & 1u)) {
                if (tid < nw) remv |= mask[i * MSTRIDE + tid];
            }
        }
        s_remv[tid] = remv;
    }
    __syncthreads();

    for (int j = tid; j < n; j += blockDim.x)
        out[spos[j] * 6 + 5] = ((s_remv[j >> 5] >> (j & 31)) & 1u) ? 0.0f : 1.0f;
}

// ---------------- launch ----------------
extern "C" void kernel_launch(void* const* d_in, const int* in_sizes, int n_in,
                              void* d_out, int out_size) {
    const float* probs   = (const float*)d_in[0];
    const float* deltas  = (const float*)d_in[1];
    const float* anchors = (const float*)d_in[2];
    float* out = (float*)d_out;

    int n_prop    = in_sizes[0] / 3;
    int n_anchors = in_sizes[2] / 4;
    int n_groups  = n_prop / 4;          // 4 props (12 floats = 3 float4) per thread-step

    const int nms_smem = NMS_CAP * (5 * 4 + 4 + MSTRIDE * 4);   // 156672 bytes
    cudaFuncSetAttribute(k_nms, cudaFuncAttributeMaxDynamicSharedMemorySize, nms_smem);

    k_hist<<<148, 512>>>(probs, n_groups);
    k_collect<<<296, 256>>>(probs, n_groups);
    k_rankdec<<<CAND_CAP / RC, 256>>>(deltas, anchors, out, n_anchors);
    k_nms<<<NGROUPS, 1024, nms_smem>>>(out);
}